// round 5
// baseline (speedup 1.0000x reference)
#include <cuda_runtime.h>

// Problem constants (fixed by the dataset shapes)
#define B_      8
#define NHEADS  4
#define Q_      512      // codebook entries per head (N/4)
#define L_      2048     // sequence length (innermost logits dim)
#define D_      512      // embedding dim
#define K_      3        // top-k

#define LT       32      // l-tile per block
#define NTHREADS 512
#define SEGS     4       // n-range split per (h,l)
#define NSEG     (Q_ / SEGS)   // 128

#define DCHUNK   128             // dd per phase-2 round (float4: 32 lanes x 4)
#define NROUND   (D_ / DCHUNK)   // 4
#define TPITCH   132             // tile row pitch in floats (16B-aligned, 132 mod 32 = 4)

// top-3 update, branch-light common path (v <= t2 almost always)
#define TOP3_UPDATE(v, n)                                              \
    do {                                                               \
        if ((v) > t2) {                                                \
            if ((v) > t0)      { t2=t1; i2=i1; t1=t0; i1=i0; t0=(v); i0=(n); } \
            else if ((v) > t1) { t2=t1; i2=i1; t1=(v); i1=(n); }       \
            else               { t2=(v); i2=(n); }                     \
        }                                                              \
    } while (0)

__global__ __launch_bounds__(NTHREADS)
void embed_topk_combine(const float* __restrict__ logits,
                        const float* __restrict__ e0,
                        const float* __restrict__ e1,
                        const float* __restrict__ e2,
                        const float* __restrict__ e3,
                        float* __restrict__ out)
{
    const int b   = blockIdx.y;
    const int l0  = blockIdx.x * LT;
    const int tid = threadIdx.x;

    // Overlaid SMEM region:
    //   phase 1: partial top-3 from segments 1..3   (2 x 4608 B = 9216 B)
    //   phase 2: 32 x TPITCH float transpose tile   (16896 B)
    // Lifetimes are disjoint (partials dead after the merge barrier).
    __shared__ __align__(16) char s_buf[32 * TPITCH * 4];
    float* s_pv  = (float*)s_buf;                    // [3][NHEADS][LT][K_]
    int*   s_pi  = (int*)(s_buf + (SEGS-1)*NHEADS*LT*K_*4);
    float* tile  = (float*)s_buf;                    // [LT][TPITCH]

    // merged result (persists through phase 2)
    __shared__ int   s_idx[NHEADS][LT][K_];
    __shared__ float s_w  [NHEADS][LT][K_];

    // ---------------- phase 1: split-n top-3 (MLP=8 per thread) ----------
    {
        const int l   = tid & (LT - 1);            // 0..31
        const int h   = (tid >> 5) & (NHEADS - 1); // 0..3
        const int seg = tid >> 7;                  // 0..3
        const int nb  = seg * NSEG;

        const float* p = logits
            + ((size_t)b * (NHEADS * Q_) + (size_t)h * Q_ + nb) * L_ + l0 + l;

        float t0 = -3.4e38f, t1 = -3.4e38f, t2 = -3.4e38f;
        int   i0 = 0, i1 = 0, i2 = 0;

        for (int n = 0; n < NSEG; n += 8) {
            float v0 = __ldg(p + (size_t)(n + 0) * L_);
            float v1 = __ldg(p + (size_t)(n + 1) * L_);
            float v2 = __ldg(p + (size_t)(n + 2) * L_);
            float v3 = __ldg(p + (size_t)(n + 3) * L_);
            float v4 = __ldg(p + (size_t)(n + 4) * L_);
            float v5 = __ldg(p + (size_t)(n + 5) * L_);
            float v6 = __ldg(p + (size_t)(n + 6) * L_);
            float v7 = __ldg(p + (size_t)(n + 7) * L_);
            TOP3_UPDATE(v0, nb + n + 0);
            TOP3_UPDATE(v1, nb + n + 1);
            TOP3_UPDATE(v2, nb + n + 2);
            TOP3_UPDATE(v3, nb + n + 3);
            TOP3_UPDATE(v4, nb + n + 4);
            TOP3_UPDATE(v5, nb + n + 5);
            TOP3_UPDATE(v6, nb + n + 6);
            TOP3_UPDATE(v7, nb + n + 7);
        }

        if (seg > 0) {
            int base = (((seg - 1) * NHEADS + h) * LT + l) * K_;
            s_pv[base + 0] = t0;  s_pi[base + 0] = i0;
            s_pv[base + 1] = t1;  s_pi[base + 1] = i1;
            s_pv[base + 2] = t2;  s_pi[base + 2] = i2;
        }
        __syncthreads();

        if (seg == 0) {
            #pragma unroll
            for (int s = 0; s < SEGS - 1; s++) {
                int base = ((s * NHEADS + h) * LT + l) * K_;
                #pragma unroll
                for (int k = 0; k < K_; k++) {
                    float v = s_pv[base + k];
                    int   n = s_pi[base + k];
                    TOP3_UPDATE(v, n);
                }
            }
            float w1  = expf(t1 - t0);
            float w2  = expf(t2 - t0);
            float inv = 1.0f / (1.0f + w1 + w2);
            s_w[h][l][0] = inv;
            s_w[h][l][1] = w1 * inv;
            s_w[h][l][2] = w2 * inv;
            s_idx[h][l][0] = i0;
            s_idx[h][l][1] = i1;
            s_idx[h][l][2] = i2;
        }
    }
    __syncthreads();   // also fences partials before the tile overlays them

    // ---------------- phase 2: float4 gather-combine, 4 rounds -----------
    const int warp = tid >> 5;   // 0..15
    const int lane = tid & 31;
    float* outb = out + (size_t)b * D_ * L_ + l0;

    const float4* t0_4 = (const float4*)e0;
    const float4* t1_4 = (const float4*)e1;
    const float4* t2_4 = (const float4*)e2;
    const float4* t3_4 = (const float4*)e3;

    #pragma unroll
    for (int r = 0; r < NROUND; r++) {
        const int c = r * (DCHUNK / 4) + lane;   // float4 column within row

        // warp <-> li: 12 independent LDG.128 per li (512B lines each)
        #pragma unroll
        for (int li = warp; li < LT; li += NTHREADS / 32) {
            float4 acc = make_float4(0.f, 0.f, 0.f, 0.f);
            #pragma unroll
            for (int h = 0; h < NHEADS; h++) {
                const float4* eh = (h == 0) ? t0_4 : (h == 1) ? t1_4
                                 : (h == 2) ? t2_4 : t3_4;
                #pragma unroll
                for (int k = 0; k < K_; k++) {
                    int    m = s_idx[h][li][k];
                    float  w = s_w  [h][li][k];
                    float4 v = __ldg(eh + (size_t)m * (D_ / 4) + c);
                    acc.x = fmaf(w, v.x, acc.x);
                    acc.y = fmaf(w, v.y, acc.y);
                    acc.z = fmaf(w, v.z, acc.z);
                    acc.w = fmaf(w, v.w, acc.w);
                }
            }
            // conflict-free float4 store: row li, cols 4*lane..4*lane+3
            *(float4*)&tile[li * TPITCH + 4 * lane] = acc;
        }
        __syncthreads();

        // coalesced output: lane <-> l, warp-strided over dd
        #pragma unroll
        for (int i = tid; i < DCHUNK * LT; i += NTHREADS) {
            int dd = i >> 5;         // 0..127
            int l  = i & (LT - 1);
            outb[(size_t)(r * DCHUNK + dd) * L_ + l] = tile[l * TPITCH + dd];
        }
        __syncthreads();
    }
}

extern "C" void kernel_launch(void* const* d_in, const int* in_sizes, int n_in,
                              void* d_out, int out_size)
{
    const float* logits = (const float*)d_in[0];
    const float* e0     = (const float*)d_in[1];
    const float* e1     = (const float*)d_in[2];
    const float* e2     = (const float*)d_in[3];
    const float* e3     = (const float*)d_in[4];
    float*       out    = (float*)d_out;

    dim3 grid(L_ / LT, B_);   // 64 x 8 = 512 blocks
    dim3 block(NTHREADS);
    embed_topk_combine<<<grid, block>>>(logits, e0, e1, e2, e3, out);
}